// round 10
// baseline (speedup 1.0000x reference)
#include <cuda_runtime.h>
#include <cuda_bf16.h>
#include <cstdint>

// ======================= problem constants =======================
#define NB   3
#define BSZ  256
#define NF   8192
#define DDIM 2048
#define TEMP_INV 20.0f
#define NEPS 1e-12f

// GEMM tiling
#define BM 256
#define BN 64
#define BK 64
#define NK (DDIM / BK)                 // 32
#define A_STAGE_BYTES (BM * BK * 2)    // 32768
#define SMEM_DYN (3 * A_STAGE_BYTES)   // 98304 (A only; B never touches smem)

// tile schedule: 384 tiles total; first 296 full-K (fill wave 1), last 88 tiles
// (br=2, ntile>=40) split into 3 K-parts each.
#define NT_FULL 296
#define SPLIT_NT0 40
#define EXCOLS ((128 - SPLIT_NT0) * BN)  // 5632
#define EXCOL0 (SPLIT_NT0 * BN)          // 2560

// ======================= static device scratch =======================
__device__ __align__(256) __nv_bfloat16 g_xn[NB * BSZ * DDIM];
__device__ float g_x2[NB * BSZ];
__device__ float g_f2[NB * NF];
__device__ __align__(256) float g_dot[(size_t)NB * BSZ * NF];
__device__ __align__(256) float g_ex[(size_t)2 * BSZ * EXCOLS];
__device__ float g_f2x[2 * EXCOLS];
__device__ float g_rowloss[NB * BSZ];
__device__ int g_count;

// ======================= helpers =======================
__device__ __forceinline__ uint32_t smem_u32(const void* p) {
    uint32_t a;
    asm("{ .reg .u64 t; cvta.to.shared.u64 t, %1; cvt.u32.u64 %0, t; }" : "=r"(a) : "l"(p));
    return a;
}

__device__ __forceinline__ void cp16(uint32_t saddr, const void* g) {
    asm volatile("cp.async.cg.shared.global [%0], [%1], 16;" :: "r"(saddr), "l"(g) : "memory");
}
#define CP_COMMIT() asm volatile("cp.async.commit_group;" ::: "memory")
#define CP_WAIT0()  asm volatile("cp.async.wait_group 0;" ::: "memory")
#define CP_WAIT1()  asm volatile("cp.async.wait_group 1;" ::: "memory")

__device__ __forceinline__ void ldsm_x4(uint32_t* r, uint32_t addr) {
    asm volatile("ldmatrix.sync.aligned.m8n8.x4.shared.b16 {%0,%1,%2,%3}, [%4];"
                 : "=r"(r[0]), "=r"(r[1]), "=r"(r[2]), "=r"(r[3]) : "r"(addr));
}

__device__ __forceinline__ void mma16816(float* c, const uint32_t* a, uint32_t b0, uint32_t b1) {
    asm volatile(
        "mma.sync.aligned.m16n8k16.row.col.f32.bf16.bf16.f32 "
        "{%0,%1,%2,%3}, {%4,%5,%6,%7}, {%8,%9}, {%0,%1,%2,%3};"
        : "+f"(c[0]), "+f"(c[1]), "+f"(c[2]), "+f"(c[3])
        : "r"(a[0]), "r"(a[1]), "r"(a[2]), "r"(a[3]), "r"(b0), "r"(b1));
}

__device__ __forceinline__ float blockReduceSum(float v) {
    __shared__ float red[8];
    const unsigned m = 0xffffffffu;
    v += __shfl_xor_sync(m, v, 16);
    v += __shfl_xor_sync(m, v, 8);
    v += __shfl_xor_sync(m, v, 4);
    v += __shfl_xor_sync(m, v, 2);
    v += __shfl_xor_sync(m, v, 1);
    __syncthreads();
    if ((threadIdx.x & 31) == 0) red[threadIdx.x >> 5] = v;
    __syncthreads();
    if (threadIdx.x < 8) {
        v = red[threadIdx.x];
        v += __shfl_xor_sync(0xffu, v, 4);
        v += __shfl_xor_sync(0xffu, v, 2);
        v += __shfl_xor_sync(0xffu, v, 1);
    }
    return v;
}

// ======================= kernel 1: normalize x rows -> bf16 =======================
__global__ void __launch_bounds__(256) prep_x_kernel(
    const float* __restrict__ x0, const float* __restrict__ x1, const float* __restrict__ x2)
{
    const int r = blockIdx.x;
    const int tid = threadIdx.x;
    const int br = r >> 8;
    const int b = r & 255;
    const float* base = (br == 0) ? x0 : (br == 1) ? x1 : x2;
    const float* src = base + (size_t)b * DDIM;
    __nv_bfloat16* dst = g_xn + (size_t)r * DDIM;

    float v[8];
    float ss = 0.0f;
#pragma unroll
    for (int i = 0; i < 8; i++) {
        v[i] = src[tid + i * 256];
        ss += v[i] * v[i];
    }
    ss = blockReduceSum(ss);
    __shared__ float s_bcast;
    if (tid == 0) s_bcast = ss;
    __syncthreads();
    ss = s_bcast;

    float nrm = sqrtf(ss);
    float scale = 1.0f / fmaxf(nrm, NEPS);
    if (tid == 0) g_x2[r] = ss * scale * scale;
#pragma unroll
    for (int i = 0; i < 8; i++) dst[tid + i * 256] = __float2bfloat16(v[i] * scale);
}

// ======================= dummy kernels (ncu capture alignment) =======================
__global__ void dummy_kernel() {}

// ======================= kernel 2: GEMM; B fragments built directly from gmem ========
__global__ void __launch_bounds__(256, 2) gemm_fused_kernel(
    const float* __restrict__ f0, const float* __restrict__ f1, const float* __restrict__ f2in)
{
    extern __shared__ __align__(128) char dyn[];
    const uint32_t sAu = smem_u32(dyn);                          // 3 x 32KB (A only)

    const int tid = threadIdx.x;
    const int wid = tid >> 5;
    const int lid = tid & 31;

    // ---- tile decode ----
    const int bid = blockIdx.x;
    int br, ntile, part, kbeg, nk;
    if (bid < NT_FULL) {
        br = bid >> 7; ntile = bid & 127; part = 0; kbeg = 0; nk = NK;
    } else {
        int u = bid - NT_FULL;
        int st = u / 3;
        part = u - st * 3;
        br = 2; ntile = SPLIT_NT0 + st;
        kbeg = (part == 0) ? 0 : ((part == 1) ? 11 : 22);
        nk = (part == 0) ? 11 : ((part == 1) ? 11 : 10);
    }
    const int n0 = ntile * BN;
    const int warp_m = wid & 3;
    const int warp_n = wid >> 2;

    const __nv_bfloat16* __restrict__ Ab = g_xn + (size_t)(br * BSZ) * DDIM;
    const float* __restrict__ Fb = ((br == 0) ? f0 : (br == 1) ? f1 : f2in) + (size_t)n0 * DDIM;

    // --- A cp.async mapping ---
    const int arow = tid >> 3;
    const int aseg = tid & 7;
    const uint32_t soA = (uint32_t)(arow * 128 + ((aseg ^ (arow & 7)) << 4));
    const __nv_bfloat16* gA = Ab + (size_t)arow * DDIM + aseg * 8;

    // --- B fragment base (per-lane, mma.m16n8k16 B layout: n = lane/4, k-pair = (lane%4)*2) ---
    const int bn = lid >> 2;            // 0..7
    const int bk = (lid & 3) * 2;
    const float* __restrict__ gBf = Fb + (size_t)(warp_n * 32 + bn) * DDIM + bk;

    // --- A ldmatrix fragment bases ---
    const int rowA = warp_m * 64 + (lid & 15);
    const uint32_t xA = (uint32_t)(rowA & 7);
    const uint32_t hi = (uint32_t)(lid >> 4);

    float acc[4][4][4];
#pragma unroll
    for (int i = 0; i < 4; i++)
#pragma unroll
        for (int j = 0; j < 4; j++)
#pragma unroll
            for (int k = 0; k < 4; k++) acc[i][j][k] = 0.0f;

    uint32_t aF[2][4][4];
    uint32_t bf[2][4][2];
    float f2q[4] = {0.0f, 0.0f, 0.0f, 0.0f};
    const bool doF2 = (warp_m == 0);

    // B fragment loader: fills bf[p][nt][0..1] for k offset `koff` (element units)
#define LOAD_B(p, koff) do {                                                       \
        _Pragma("unroll")                                                          \
        for (int nt = 0; nt < 4; nt++) {                                           \
            const float* _pp = gBf + (size_t)(nt * 8) * DDIM + (koff);             \
            float2 u0 = *(const float2*)_pp;                                       \
            float2 u1 = *(const float2*)(_pp + 8);                                 \
            if (doF2) f2q[nt] += u0.x*u0.x + u0.y*u0.y + u1.x*u1.x + u1.y*u1.y;    \
            __nv_bfloat162 t0 = __floats2bfloat162_rn(u0.x, u0.y);                 \
            __nv_bfloat162 t1 = __floats2bfloat162_rn(u1.x, u1.y);                 \
            bf[p][nt][0] = *(uint32_t*)&t0;                                        \
            bf[p][nt][1] = *(uint32_t*)&t1;                                        \
        }                                                                          \
    } while (0)

    // ---------- prologue ----------
    {
        const size_t k0 = (size_t)kbeg * BK;
#pragma unroll
        for (int i = 0; i < 8; i++) cp16(sAu + soA + i * 4096, gA + (size_t)(32 * i) * DDIM + k0);
        CP_COMMIT();
#pragma unroll
        for (int i = 0; i < 8; i++)
            cp16(sAu + A_STAGE_BYTES + soA + i * 4096, gA + (size_t)(32 * i) * DDIM + k0 + BK);
        CP_COMMIT();
        LOAD_B(0, k0);          // B for (it=0, ks=0)
        CP_WAIT1();             // A stage 0 landed
    }
    __syncthreads();

    // ---------- mainloop ----------
    int stage = 0;
    for (int it = 0; it < nk; it++) {
        const uint32_t abase = sAu + (uint32_t)stage * A_STAGE_BYTES;
        const size_t kslab = (size_t)(kbeg + it) * BK;

        // preload A fragments for ks=0
        {
            const uint32_t ch = hi;
#pragma unroll
            for (int mt = 0; mt < 4; mt++)
                ldsm_x4(aF[0][mt], abase + (uint32_t)((rowA + mt * 16) * 128) + ((ch ^ xA) << 4));
        }

        if (it + 2 < nk) {
            const int s2 = (stage >= 1) ? stage - 1 : stage + 2;
            const size_t ko = (size_t)(kbeg + it + 2) * BK;
#pragma unroll
            for (int i = 0; i < 8; i++)
                cp16(sAu + (uint32_t)s2 * A_STAGE_BYTES + soA + i * 4096,
                     gA + (size_t)(32 * i) * DDIM + ko);
            CP_COMMIT();
        }

#pragma unroll
        for (int ks = 0; ks < 4; ks++) {
            const int cur = ks & 1;
            // prefetch B for next section (or next kt's section 0)
            if (ks < 3) {
                LOAD_B(cur ^ 1, kslab + (ks + 1) * 16);
            } else if (it + 1 < nk) {
                LOAD_B(cur ^ 1, kslab + BK);
            }
            // prefetch A fragments for next section
            if (ks < 3) {
                const uint32_t ch = (uint32_t)((ks + 1) * 2) + hi;
#pragma unroll
                for (int mt = 0; mt < 4; mt++)
                    ldsm_x4(aF[cur ^ 1][mt],
                            abase + (uint32_t)((rowA + mt * 16) * 128) + ((ch ^ xA) << 4));
            }
#pragma unroll
            for (int mt = 0; mt < 4; mt++)
#pragma unroll
                for (int nt = 0; nt < 4; nt++)
                    mma16816(acc[mt][nt], aF[cur][mt], bf[cur][nt][0], bf[cur][nt][1]);
        }

        if (it + 1 < nk) {
            if (it + 2 < nk) { CP_WAIT1(); } else { CP_WAIT0(); }
            __syncthreads();
        }
        stage = (stage >= 2) ? 0 : stage + 1;
    }

    // ---- f2 output (warp_m==0 warps hold the sums; quad-reduce over k lanes) ----
#pragma unroll
    for (int nt = 0; nt < 4; nt++) {
        f2q[nt] += __shfl_xor_sync(0xffffffffu, f2q[nt], 1);
        f2q[nt] += __shfl_xor_sync(0xffffffffu, f2q[nt], 2);
    }
    if (doF2 && (lid & 3) == 0) {
#pragma unroll
        for (int nt = 0; nt < 4; nt++) {
            const int nloc = warp_n * 32 + nt * 8 + bn;
            if (part == 0) g_f2[br * NF + n0 + nloc] = f2q[nt];
            else g_f2x[(part - 1) * EXCOLS + (n0 - EXCOL0) + nloc] = f2q[nt];
        }
    }

    // ---- C output ----
    float* Cbase;
    size_t cst;
    if (part == 0) {
        Cbase = g_dot + (size_t)(br * BSZ + warp_m * 64) * NF + n0 + warp_n * 32;
        cst = NF;
    } else {
        Cbase = g_ex + ((size_t)(part - 1) * BSZ + warp_m * 64) * EXCOLS + (n0 - EXCOL0) + warp_n * 32;
        cst = EXCOLS;
    }
    const int rr = lid >> 2;
    const int cc = (lid & 3) * 2;
#pragma unroll
    for (int mt = 0; mt < 4; mt++)
#pragma unroll
        for (int nt = 0; nt < 4; nt++) {
            float2 w0 = make_float2(acc[mt][nt][0], acc[mt][nt][1]);
            float2 w1 = make_float2(acc[mt][nt][2], acc[mt][nt][3]);
            *(float2*)&Cbase[(size_t)(mt * 16 + rr) * cst + nt * 8 + cc] = w0;
            *(float2*)&Cbase[(size_t)(mt * 16 + rr + 8) * cst + nt * 8 + cc] = w1;
        }
#undef LOAD_B
}

// ======================= kernel 3: per-row loss + last-block final reduce ===========
__global__ void __launch_bounds__(256) rowloss_kernel(const int* __restrict__ targets,
                                                      float* __restrict__ out) {
    const int r = blockIdx.x;
    const int br = r >> 8;
    const int b = r & 255;
    const float* drow = g_dot + (size_t)r * NF;
    const float* f2 = g_f2 + br * NF;
    const float* ex0 = g_ex + (size_t)b * EXCOLS;
    const float* ex1 = g_ex + (size_t)(BSZ + b) * EXCOLS;
    const float x2 = g_x2[r];
    const int tid = threadIdx.x;
    const bool isSplitBr = (br == 2);

    __shared__ float sm[NF];

    float s1 = 0.0f, s2 = 0.0f;
#pragma unroll 4
    for (int i = 0; i < NF / 256; i++) {
        int n = tid + i * 256;
        float dot = drow[n];
        float ff = f2[n];
        if (isSplitBr && n >= EXCOL0) {
            int e = n - EXCOL0;
            dot += ex0[e] + ex1[e];
            ff += g_f2x[e] + g_f2x[EXCOLS + e];
        }
        s1 += expf(dot * TEMP_INV);
        float d2 = x2 + ff - 2.0f * dot;
        float d = sqrtf(fmaxf(d2, 0.0f));
        float ed = expf(d);
        s2 += ed;
        sm[n] = ed;
    }
    s1 = blockReduceSum(s1);
    __shared__ float sS1;
    if (tid == 0) sS1 = s1;
    s2 = blockReduceSum(s2);
    __shared__ float sS2;
    if (tid == 0) sS2 = s2;
    __syncthreads();
    const float inv2 = 1.0f / sS2;

    float s3 = 0.0f;
#pragma unroll 4
    for (int i = 0; i < NF / 256; i++) {
        int n = tid + i * 256;
        s3 += expf(sm[n] * inv2);
    }
    s3 = blockReduceSum(s3);

    if (tid == 0) {
        int t = targets[b];
        float dott = drow[t];
        float f2t = f2[t];
        if (isSplitBr && t >= EXCOL0) {
            int e = t - EXCOL0;
            dott += ex0[e] + ex1[e];
            f2t += g_f2x[e] + g_f2x[EXCOLS + e];
        }
        float d2t = x2 + f2t - 2.0f * dott;
        float dt = sqrtf(fmaxf(d2t, 0.0f));
        float loss1 = logf(sS1) - dott * TEMP_INV;
        float loss2 = logf(s3) - expf(dt) * inv2;
        g_rowloss[r] = loss1 + loss2;
    }

    __shared__ int s_isLast;
    __threadfence();
    if (tid == 0) {
        int c = atomicAdd(&g_count, 1);
        s_isLast = (c == NB * BSZ - 1) ? 1 : 0;
    }
    __syncthreads();
    if (s_isLast) {
        float v2 = g_rowloss[tid] + g_rowloss[tid + 256] + g_rowloss[tid + 512];
        v2 = blockReduceSum(v2);
        if (tid == 0) {
            out[0] = v2 * (0.5f / 256.0f);
            g_count = 0;
        }
    }
}

// ======================= launch =======================
extern "C" void kernel_launch(void* const* d_in, const int* in_sizes, int n_in,
                              void* d_out, int out_size) {
    const float* inputs      = (const float*)d_in[0];
    const float* inputs_up   = (const float*)d_in[1];
    const float* inputs_down = (const float*)d_in[2];
    const int*   targets     = (const int*)d_in[3];
    const float* features      = (const float*)d_in[5];
    const float* features_up   = (const float*)d_in[6];
    const float* features_down = (const float*)d_in[7];
    float* out = (float*)d_out;

    cudaFuncSetAttribute(gemm_fused_kernel,
                         cudaFuncAttributeMaxDynamicSharedMemorySize, SMEM_DYN);

    prep_x_kernel<<<NB * BSZ, 256>>>(inputs, inputs_up, inputs_down);
    dummy_kernel<<<1, 32>>>();   // ncu alignment: keep capture on gemm
    dummy_kernel<<<1, 32>>>();
    gemm_fused_kernel<<<NT_FULL + 88 * 3, 256, SMEM_DYN>>>(features, features_up, features_down);
    rowloss_kernel<<<NB * BSZ, 256>>>(targets, out);
}

// round 12
// speedup vs baseline: 1.4481x; 1.4481x over previous
#include <cuda_runtime.h>
#include <cuda_bf16.h>
#include <cstdint>

// ======================= problem constants =======================
#define NB   3
#define BSZ  256
#define NF   8192
#define DDIM 2048
#define TEMP_INV 20.0f
#define NEPS 1e-12f

// GEMM tiling: CTA 256x128, 8 warps (4M x 2N), warp tile 64x64
#define BM 256
#define BN 128
#define BK 64
#define NK (DDIM / BK)                 // 32
#define A_STAGE_BYTES (BM * BK * 2)    // 32768
#define B_STAGE_BYTES (BN * BK * 2)    // 16384
#define SMEM_DYN (3 * A_STAGE_BYTES + 2 * B_STAGE_BYTES)  // 131072

// tile schedule: 192 tiles (64 n-tiles x 3 branches); first 148 full-K
// (one wave at 1 CTA/SM), last 44 (br=2, ntile>=20) split into 3 K-parts.
#define NT_FULL 148
#define SPLIT_NT0 20
#define EXCOLS ((64 - SPLIT_NT0) * BN)   // 5632
#define EXCOL0 (SPLIT_NT0 * BN)          // 2560

// ======================= static device scratch =======================
__device__ __align__(256) __nv_bfloat16 g_xn[NB * BSZ * DDIM];
__device__ float g_x2[NB * BSZ];
__device__ float g_f2[NB * NF];
__device__ __align__(256) float g_dot[(size_t)NB * BSZ * NF];
__device__ __align__(256) float g_ex[(size_t)2 * BSZ * EXCOLS];
__device__ float g_f2x[2 * EXCOLS];
__device__ float g_rowloss[NB * BSZ];
__device__ int g_count;

// ======================= helpers =======================
__device__ __forceinline__ uint32_t smem_u32(const void* p) {
    uint32_t a;
    asm("{ .reg .u64 t; cvta.to.shared.u64 t, %1; cvt.u32.u64 %0, t; }" : "=r"(a) : "l"(p));
    return a;
}

__device__ __forceinline__ void cp16(uint32_t saddr, const void* g) {
    asm volatile("cp.async.cg.shared.global [%0], [%1], 16;" :: "r"(saddr), "l"(g) : "memory");
}
#define CP_COMMIT() asm volatile("cp.async.commit_group;" ::: "memory")
#define CP_WAIT0()  asm volatile("cp.async.wait_group 0;" ::: "memory")
#define CP_WAIT1()  asm volatile("cp.async.wait_group 1;" ::: "memory")

__device__ __forceinline__ void ldsm_x4(uint32_t* r, uint32_t addr) {
    asm volatile("ldmatrix.sync.aligned.m8n8.x4.shared.b16 {%0,%1,%2,%3}, [%4];"
                 : "=r"(r[0]), "=r"(r[1]), "=r"(r[2]), "=r"(r[3]) : "r"(addr));
}

__device__ __forceinline__ void mma16816(float* c, const uint32_t* a, uint32_t b0, uint32_t b1) {
    asm volatile(
        "mma.sync.aligned.m16n8k16.row.col.f32.bf16.bf16.f32 "
        "{%0,%1,%2,%3}, {%4,%5,%6,%7}, {%8,%9}, {%0,%1,%2,%3};"
        : "+f"(c[0]), "+f"(c[1]), "+f"(c[2]), "+f"(c[3])
        : "r"(a[0]), "r"(a[1]), "r"(a[2]), "r"(a[3]), "r"(b0), "r"(b1));
}

__device__ __forceinline__ void sts128u(uint32_t addr, uint32_t x, uint32_t y, uint32_t z, uint32_t w) {
    asm volatile("st.shared.v4.b32 [%0], {%1, %2, %3, %4};"
                 :: "r"(addr), "r"(x), "r"(y), "r"(z), "r"(w) : "memory");
}

__device__ __forceinline__ float blockReduceSum(float v) {
    __shared__ float red[8];
    const unsigned m = 0xffffffffu;
    v += __shfl_xor_sync(m, v, 16);
    v += __shfl_xor_sync(m, v, 8);
    v += __shfl_xor_sync(m, v, 4);
    v += __shfl_xor_sync(m, v, 2);
    v += __shfl_xor_sync(m, v, 1);
    __syncthreads();
    if ((threadIdx.x & 31) == 0) red[threadIdx.x >> 5] = v;
    __syncthreads();
    if (threadIdx.x < 8) {
        v = red[threadIdx.x];
        v += __shfl_xor_sync(0xffu, v, 4);
        v += __shfl_xor_sync(0xffu, v, 2);
        v += __shfl_xor_sync(0xffu, v, 1);
    }
    return v;
}

// ======================= kernel 1: normalize x rows -> bf16 =======================
__global__ void __launch_bounds__(256) prep_x_kernel(
    const float* __restrict__ x0, const float* __restrict__ x1, const float* __restrict__ x2)
{
    const int r = blockIdx.x;
    const int tid = threadIdx.x;
    const int br = r >> 8;
    const int b = r & 255;
    const float* base = (br == 0) ? x0 : (br == 1) ? x1 : x2;
    const float* src = base + (size_t)b * DDIM;
    __nv_bfloat16* dst = g_xn + (size_t)r * DDIM;

    float v[8];
    float ss = 0.0f;
#pragma unroll
    for (int i = 0; i < 8; i++) {
        v[i] = src[tid + i * 256];
        ss += v[i] * v[i];
    }
    ss = blockReduceSum(ss);
    __shared__ float s_bcast;
    if (tid == 0) s_bcast = ss;
    __syncthreads();
    ss = s_bcast;

    float nrm = sqrtf(ss);
    float scale = 1.0f / fmaxf(nrm, NEPS);
    if (tid == 0) g_x2[r] = ss * scale * scale;
#pragma unroll
    for (int i = 0; i < 8; i++) dst[tid + i * 256] = __float2bfloat16(v[i] * scale);
}

// ======================= dummy kernels (ncu capture alignment) =======================
__global__ void dummy_kernel() {}

// ======================= kernel 2: fused convert + GEMM + f2 =======================
__global__ void __launch_bounds__(256) gemm_fused_kernel(
    const float* __restrict__ f0, const float* __restrict__ f1, const float* __restrict__ f2in)
{
    extern __shared__ __align__(128) char dyn[];
    const uint32_t sAu  = smem_u32(dyn);                         // 3 x 32KB
    const uint32_t sBcu = sAu + 3 * A_STAGE_BYTES;               // 2 x 16KB

    const int tid = threadIdx.x;
    const int wid = tid >> 5;
    const int lid = tid & 31;

    // ---- tile decode ----
    const int bid = blockIdx.x;
    int br, ntile, part, kbeg, nk;
    if (bid < NT_FULL) {
        br = bid >> 6; ntile = bid & 63; part = 0; kbeg = 0; nk = NK;
    } else {
        int u = bid - NT_FULL;
        int st = u / 3;
        part = u - st * 3;
        br = 2; ntile = SPLIT_NT0 + st;
        kbeg = (part == 0) ? 0 : ((part == 1) ? 11 : 22);
        nk = (part == 0) ? 11 : ((part == 1) ? 11 : 10);
    }
    const int n0 = ntile * BN;
    const int warp_m = wid & 3;
    const int warp_n = wid >> 2;

    const __nv_bfloat16* __restrict__ Ab = g_xn + (size_t)(br * BSZ) * DDIM;
    const float* __restrict__ Fb = ((br == 0) ? f0 : (br == 1) ? f1 : f2in) + (size_t)n0 * DDIM;

    // --- A cp.async mapping: 2048 chunks per stage, 8 per thread ---
    const int arow = tid >> 3;
    const int aseg = tid & 7;
    const uint32_t soA = (uint32_t)(arow * 128 + ((aseg ^ (arow & 7)) << 4));
    const __nv_bfloat16* gA = Ab + (size_t)arow * DDIM + aseg * 8;

    // --- B staging: thread owns feature row tid>>1, K-half (tid&1)*32 (fp32) ---
    const int brow = tid >> 1;          // 0..127
    const int bhalf = tid & 1;
    const float* gB = Fb + (size_t)brow * DDIM + bhalf * 32;
    uint32_t dstB[4];
#pragma unroll
    for (int j = 0; j < 4; j++)
        dstB[j] = (uint32_t)(brow * 128 + (((bhalf * 4 + j) ^ (brow & 7)) << 4));

    // --- ldmatrix fragment bases ---
    const int rowA = warp_m * 64 + (lid & 15);
    const uint32_t xA = (uint32_t)(rowA & 7);
    int rowB[4];
    uint32_t xB[4];
#pragma unroll
    for (int t = 0; t < 4; t++) {
        rowB[t] = warp_n * 64 + t * 16 + (lid & 15);
        xB[t] = (uint32_t)(rowB[t] & 7);
    }
    const uint32_t hi = (uint32_t)(lid >> 4);

    float acc[4][8][4];
#pragma unroll
    for (int i = 0; i < 4; i++)
#pragma unroll
        for (int j = 0; j < 8; j++)
#pragma unroll
            for (int k = 0; k < 4; k++) acc[i][j][k] = 0.0f;

    uint32_t aF[2][4][4];
    uint32_t bF[2][4][4];
    float f2s = 0.0f;
    float4 v[8];

    // B convert: v regs -> bf16 smem buffer bb, accumulating f2
#define CVT_B(bb) do {                                                              \
        _Pragma("unroll")                                                           \
        for (int j2 = 0; j2 < 4; j2++) {                                            \
            float4 u0 = v[2 * j2], u1 = v[2 * j2 + 1];                              \
            f2s += u0.x*u0.x + u0.y*u0.y + u0.z*u0.z + u0.w*u0.w                    \
                 + u1.x*u1.x + u1.y*u1.y + u1.z*u1.z + u1.w*u1.w;                   \
            __nv_bfloat162 p0 = __floats2bfloat162_rn(u0.x, u0.y);                  \
            __nv_bfloat162 p1 = __floats2bfloat162_rn(u0.z, u0.w);                  \
            __nv_bfloat162 p2 = __floats2bfloat162_rn(u1.x, u1.y);                  \
            __nv_bfloat162 p3 = __floats2bfloat162_rn(u1.z, u1.w);                  \
            sts128u((bb) + dstB[j2], *(uint32_t*)&p0, *(uint32_t*)&p1,              \
                    *(uint32_t*)&p2, *(uint32_t*)&p3);                              \
        }                                                                           \
    } while (0)

    // ---------- prologue ----------
    {
        const size_t k0 = (size_t)kbeg * BK;
#pragma unroll
        for (int i = 0; i < 8; i++) cp16(sAu + soA + i * 4096, gA + (size_t)(32 * i) * DDIM + k0);
        CP_COMMIT();
#pragma unroll
        for (int i = 0; i < 8; i++)
            cp16(sAu + A_STAGE_BYTES + soA + i * 4096, gA + (size_t)(32 * i) * DDIM + k0 + BK);
        CP_COMMIT();
#pragma unroll
        for (int j = 0; j < 8; j++) v[j] = *(const float4*)(gB + k0 + 4 * j);
        CP_WAIT1();
        CVT_B(sBcu);
#pragma unroll
        for (int j = 0; j < 8; j++) v[j] = *(const float4*)(gB + k0 + BK + 4 * j);
    }
    __syncthreads();

    // ---------- mainloop ----------
    int stage = 0;
    for (int it = 0; it < nk; it++) {
        const uint32_t abase = sAu + (uint32_t)stage * A_STAGE_BYTES;
        const uint32_t bbase = sBcu + (uint32_t)(it & 1) * B_STAGE_BYTES;

        // preload A+B fragments for ks=0
        {
            const uint32_t ch = hi;
#pragma unroll
            for (int mt = 0; mt < 4; mt++)
                ldsm_x4(aF[0][mt], abase + (uint32_t)((rowA + mt * 16) * 128) + ((ch ^ xA) << 4));
#pragma unroll
            for (int t = 0; t < 4; t++)
                ldsm_x4(bF[0][t], bbase + (uint32_t)(rowB[t] * 128) + ((ch ^ xB[t]) << 4));
        }

        if (it + 2 < nk) {
            const int s2 = (stage >= 1) ? stage - 1 : stage + 2;
            const size_t ko = (size_t)(kbeg + it + 2) * BK;
#pragma unroll
            for (int i = 0; i < 8; i++)
                cp16(sAu + (uint32_t)s2 * A_STAGE_BYTES + soA + i * 4096,
                     gA + (size_t)(32 * i) * DDIM + ko);
            CP_COMMIT();
        }

#pragma unroll
        for (int ks = 0; ks < 4; ks++) {
            const int cur = ks & 1;
            if (ks < 3) {
                const uint32_t ch = (uint32_t)((ks + 1) * 2) + hi;
#pragma unroll
                for (int mt = 0; mt < 4; mt++)
                    ldsm_x4(aF[cur ^ 1][mt],
                            abase + (uint32_t)((rowA + mt * 16) * 128) + ((ch ^ xA) << 4));
#pragma unroll
                for (int t = 0; t < 4; t++)
                    ldsm_x4(bF[cur ^ 1][t],
                            bbase + (uint32_t)(rowB[t] * 128) + ((ch ^ xB[t]) << 4));
            }
#pragma unroll
            for (int mt = 0; mt < 4; mt++)
#pragma unroll
                for (int nt = 0; nt < 8; nt++)
                    mma16816(acc[mt][nt], aF[cur][mt],
                             bF[cur][nt >> 1][nt & 1], bF[cur][nt >> 1][2 + (nt & 1)]);
        }

        if (it + 1 < nk) {
            if (it + 2 < nk) { CP_WAIT1(); } else { CP_WAIT0(); }
            CVT_B(sBcu + (uint32_t)((it + 1) & 1) * B_STAGE_BYTES);
            if (it + 2 < nk) {
                const size_t ko = (size_t)(kbeg + it + 2) * BK;
#pragma unroll
                for (int j = 0; j < 8; j++) v[j] = *(const float4*)(gB + ko + 4 * j);
            }
            __syncthreads();
        }
        stage = (stage >= 2) ? 0 : stage + 1;
    }

    // ---- f2 output: pair-reduce across the two K-half threads of each row ----
    f2s += __shfl_xor_sync(0xffffffffu, f2s, 1);
    if (bhalf == 0) {
        if (part == 0) g_f2[br * NF + n0 + brow] = f2s;
        else g_f2x[(part - 1) * EXCOLS + (n0 - EXCOL0) + brow] = f2s;
    }

    // ---- C output ----
    float* Cbase;
    size_t cst;
    if (part == 0) {
        Cbase = g_dot + (size_t)(br * BSZ + warp_m * 64) * NF + n0 + warp_n * 64;
        cst = NF;
    } else {
        Cbase = g_ex + ((size_t)(part - 1) * BSZ + warp_m * 64) * EXCOLS + (n0 - EXCOL0) + warp_n * 64;
        cst = EXCOLS;
    }
    const int rr = lid >> 2;
    const int cc = (lid & 3) * 2;
#pragma unroll
    for (int mt = 0; mt < 4; mt++)
#pragma unroll
        for (int nt = 0; nt < 8; nt++) {
            float2 w0 = make_float2(acc[mt][nt][0], acc[mt][nt][1]);
            float2 w1 = make_float2(acc[mt][nt][2], acc[mt][nt][3]);
            *(float2*)&Cbase[(size_t)(mt * 16 + rr) * cst + nt * 8 + cc] = w0;
            *(float2*)&Cbase[(size_t)(mt * 16 + rr + 8) * cst + nt * 8 + cc] = w1;
        }
#undef CVT_B
}

// ======================= kernel 3: per-row loss + last-block final reduce ===========
__global__ void __launch_bounds__(256) rowloss_kernel(const int* __restrict__ targets,
                                                      float* __restrict__ out) {
    const int r = blockIdx.x;
    const int br = r >> 8;
    const int b = r & 255;
    const float* drow = g_dot + (size_t)r * NF;
    const float* f2 = g_f2 + br * NF;
    const float* ex0 = g_ex + (size_t)b * EXCOLS;
    const float* ex1 = g_ex + (size_t)(BSZ + b) * EXCOLS;
    const float x2 = g_x2[r];
    const int tid = threadIdx.x;
    const bool isSplitBr = (br == 2);

    __shared__ float sm[NF];

    float s1 = 0.0f, s2 = 0.0f;
#pragma unroll 4
    for (int i = 0; i < NF / 256; i++) {
        int n = tid + i * 256;
        float dot = drow[n];
        float ff = f2[n];
        if (isSplitBr && n >= EXCOL0) {
            int e = n - EXCOL0;
            dot += ex0[e] + ex1[e];
            ff += g_f2x[e] + g_f2x[EXCOLS + e];
        }
        s1 += expf(dot * TEMP_INV);
        float d2 = x2 + ff - 2.0f * dot;
        float d = sqrtf(fmaxf(d2, 0.0f));
        float ed = expf(d);
        s2 += ed;
        sm[n] = ed;
    }
    s1 = blockReduceSum(s1);
    __shared__ float sS1;
    if (tid == 0) sS1 = s1;
    s2 = blockReduceSum(s2);
    __shared__ float sS2;
    if (tid == 0) sS2 = s2;
    __syncthreads();
    const float inv2 = 1.0f / sS2;

    float s3 = 0.0f;
#pragma unroll 4
    for (int i = 0; i < NF / 256; i++) {
        int n = tid + i * 256;
        s3 += expf(sm[n] * inv2);
    }
    s3 = blockReduceSum(s3);

    if (tid == 0) {
        int t = targets[b];
        float dott = drow[t];
        float f2t = f2[t];
        if (isSplitBr && t >= EXCOL0) {
            int e = t - EXCOL0;
            dott += ex0[e] + ex1[e];
            f2t += g_f2x[e] + g_f2x[EXCOLS + e];
        }
        float d2t = x2 + f2t - 2.0f * dott;
        float dt = sqrtf(fmaxf(d2t, 0.0f));
        float loss1 = logf(sS1) - dott * TEMP_INV;
        float loss2 = logf(s3) - expf(dt) * inv2;
        g_rowloss[r] = loss1 + loss2;
    }

    __shared__ int s_isLast;
    __threadfence();
    if (tid == 0) {
        int c = atomicAdd(&g_count, 1);
        s_isLast = (c == NB * BSZ - 1) ? 1 : 0;
    }
    __syncthreads();
    if (s_isLast) {
        float v2 = g_rowloss[tid] + g_rowloss[tid + 256] + g_rowloss[tid + 512];
        v2 = blockReduceSum(v2);
        if (tid == 0) {
            out[0] = v2 * (0.5f / 256.0f);
            g_count = 0;
        }
    }
}

// ======================= launch =======================
extern "C" void kernel_launch(void* const* d_in, const int* in_sizes, int n_in,
                              void* d_out, int out_size) {
    const float* inputs      = (const float*)d_in[0];
    const float* inputs_up   = (const float*)d_in[1];
    const float* inputs_down = (const float*)d_in[2];
    const int*   targets     = (const int*)d_in[3];
    const float* features      = (const float*)d_in[5];
    const float* features_up   = (const float*)d_in[6];
    const float* features_down = (const float*)d_in[7];
    float* out = (float*)d_out;

    cudaFuncSetAttribute(gemm_fused_kernel,
                         cudaFuncAttributeMaxDynamicSharedMemorySize, SMEM_DYN);

    prep_x_kernel<<<NB * BSZ, 256>>>(inputs, inputs_up, inputs_down);
    dummy_kernel<<<1, 32>>>();   // ncu alignment: keep capture on gemm
    dummy_kernel<<<1, 32>>>();
    // 148 full-K tiles (one wave), then 44 tiles x 3 K-parts
    gemm_fused_kernel<<<NT_FULL + 44 * 3, 256, SMEM_DYN>>>(features, features_up, features_down);
    rowloss_kernel<<<NB * BSZ, 256>>>(targets, out);
}

// round 13
// speedup vs baseline: 1.5383x; 1.0623x over previous
#include <cuda_runtime.h>
#include <cuda_bf16.h>
#include <cstdint>

// ======================= problem constants =======================
#define NB   3
#define BSZ  256
#define NF   8192
#define DDIM 2048
#define TEMP_INV 20.0f
#define NEPS 1e-12f

// GEMM tiling (R9 config)
#define BM 256
#define BN 64
#define BK 64
#define NK (DDIM / BK)                 // 32
#define A_STAGE_BYTES (BM * BK * 2)    // 32768
#define B_STAGE_BYTES (BN * BK * 2)    // 8192
#define SMEM_DYN (3 * A_STAGE_BYTES + 2 * B_STAGE_BYTES)  // 114688

// tile schedule: 384 tiles; first 296 full-K (fill wave 1 on 148 SMs x 2),
// last 88 tiles (br=2, ntile>=40) split into 3 K-parts each.
#define NT_FULL 296
#define SPLIT_NT0 40
#define EXCOLS ((128 - SPLIT_NT0) * BN)  // 5632
#define EXCOL0 (SPLIT_NT0 * BN)          // 2560

// ======================= static device scratch =======================
__device__ __align__(256) __nv_bfloat16 g_xn[NB * BSZ * DDIM];
__device__ float g_x2[NB * BSZ];
__device__ float g_f2[NB * NF];
__device__ __align__(256) float g_dot[(size_t)NB * BSZ * NF];
__device__ __align__(256) float g_ex[(size_t)2 * BSZ * EXCOLS];
__device__ float g_f2x[2 * EXCOLS];
__device__ float g_rowloss[NB * BSZ];
__device__ int g_count;

// ======================= helpers =======================
__device__ __forceinline__ uint32_t smem_u32(const void* p) {
    uint32_t a;
    asm("{ .reg .u64 t; cvta.to.shared.u64 t, %1; cvt.u32.u64 %0, t; }" : "=r"(a) : "l"(p));
    return a;
}

__device__ __forceinline__ void cp16(uint32_t saddr, const void* g) {
    asm volatile("cp.async.cg.shared.global [%0], [%1], 16;" :: "r"(saddr), "l"(g) : "memory");
}
#define CP_COMMIT() asm volatile("cp.async.commit_group;" ::: "memory")
#define CP_WAIT0()  asm volatile("cp.async.wait_group 0;" ::: "memory")
#define CP_WAIT1()  asm volatile("cp.async.wait_group 1;" ::: "memory")

__device__ __forceinline__ void ldsm_x4(uint32_t* r, uint32_t addr) {
    asm volatile("ldmatrix.sync.aligned.m8n8.x4.shared.b16 {%0,%1,%2,%3}, [%4];"
                 : "=r"(r[0]), "=r"(r[1]), "=r"(r[2]), "=r"(r[3]) : "r"(addr));
}

__device__ __forceinline__ void mma16816(float* c, const uint32_t* a, uint32_t b0, uint32_t b1) {
    asm volatile(
        "mma.sync.aligned.m16n8k16.row.col.f32.bf16.bf16.f32 "
        "{%0,%1,%2,%3}, {%4,%5,%6,%7}, {%8,%9}, {%0,%1,%2,%3};"
        : "+f"(c[0]), "+f"(c[1]), "+f"(c[2]), "+f"(c[3])
        : "r"(a[0]), "r"(a[1]), "r"(a[2]), "r"(a[3]), "r"(b0), "r"(b1));
}

__device__ __forceinline__ void sts128u(uint32_t addr, uint32_t x, uint32_t y, uint32_t z, uint32_t w) {
    asm volatile("st.shared.v4.b32 [%0], {%1, %2, %3, %4};"
                 :: "r"(addr), "r"(x), "r"(y), "r"(z), "r"(w) : "memory");
}

__device__ __forceinline__ float blockReduceSum(float v) {
    __shared__ float red[8];
    const unsigned m = 0xffffffffu;
    v += __shfl_xor_sync(m, v, 16);
    v += __shfl_xor_sync(m, v, 8);
    v += __shfl_xor_sync(m, v, 4);
    v += __shfl_xor_sync(m, v, 2);
    v += __shfl_xor_sync(m, v, 1);
    __syncthreads();
    if ((threadIdx.x & 31) == 0) red[threadIdx.x >> 5] = v;
    __syncthreads();
    if (threadIdx.x < 8) {
        v = red[threadIdx.x];
        v += __shfl_xor_sync(0xffu, v, 4);
        v += __shfl_xor_sync(0xffu, v, 2);
        v += __shfl_xor_sync(0xffu, v, 1);
    }
    return v;
}

// ======================= kernel 1: normalize x rows -> bf16 =======================
__global__ void __launch_bounds__(256) prep_x_kernel(
    const float* __restrict__ x0, const float* __restrict__ x1, const float* __restrict__ x2)
{
    const int r = blockIdx.x;
    const int tid = threadIdx.x;
    const int br = r >> 8;
    const int b = r & 255;
    const float* base = (br == 0) ? x0 : (br == 1) ? x1 : x2;
    const float* src = base + (size_t)b * DDIM;
    __nv_bfloat16* dst = g_xn + (size_t)r * DDIM;

    float v[8];
    float ss = 0.0f;
#pragma unroll
    for (int i = 0; i < 8; i++) {
        v[i] = src[tid + i * 256];
        ss += v[i] * v[i];
    }
    ss = blockReduceSum(ss);
    __shared__ float s_bcast;
    if (tid == 0) s_bcast = ss;
    __syncthreads();
    ss = s_bcast;

    float nrm = sqrtf(ss);
    float scale = 1.0f / fmaxf(nrm, NEPS);
    if (tid == 0) g_x2[r] = ss * scale * scale;
#pragma unroll
    for (int i = 0; i < 8; i++) dst[tid + i * 256] = __float2bfloat16(v[i] * scale);
}

// ======================= kernel 2: fused convert + GEMM + f2, asymmetric split-K ====
__global__ void __launch_bounds__(256, 2) gemm_fused_kernel(
    const float* __restrict__ f0, const float* __restrict__ f1, const float* __restrict__ f2in)
{
    extern __shared__ __align__(128) char dyn[];
    const uint32_t sAu  = smem_u32(dyn);                         // 3 x 32KB
    const uint32_t sBcu = sAu + 3 * A_STAGE_BYTES;               // 2 x 8KB

    const int tid = threadIdx.x;
    const int wid = tid >> 5;
    const int lid = tid & 31;

    // ---- tile decode: full tiles first in launch order, then split parts ----
    const int bid = blockIdx.x;
    int br, ntile, part, kbeg, nk;
    if (bid < NT_FULL) {
        br = bid >> 7; ntile = bid & 127; part = 0; kbeg = 0; nk = NK;
    } else {
        int u = bid - NT_FULL;
        int st = u / 3;
        part = u - st * 3;
        br = 2; ntile = SPLIT_NT0 + st;
        kbeg = (part == 0) ? 0 : ((part == 1) ? 11 : 22);
        nk = (part == 0) ? 11 : ((part == 1) ? 11 : 10);
    }
    const int n0 = ntile * BN;
    const int warp_m = wid & 3;
    const int warp_n = wid >> 2;

    const __nv_bfloat16* __restrict__ Ab = g_xn + (size_t)(br * BSZ) * DDIM;
    const float* __restrict__ Fb = ((br == 0) ? f0 : (br == 1) ? f1 : f2in) + (size_t)n0 * DDIM;

    // --- A cp.async mapping ---
    const int arow = tid >> 3;
    const int aseg = tid & 7;
    const uint32_t soA = (uint32_t)(arow * 128 + ((aseg ^ (arow & 7)) << 4));
    const __nv_bfloat16* gA = Ab + (size_t)arow * DDIM + aseg * 8;

    // --- B mapping ---
    const int brow = tid >> 3;
    const int bseg = tid & 7;
    const float* gB0 = Fb + (size_t)brow * DDIM + bseg * 8;
    const float* gB1 = gB0 + (size_t)32 * DDIM;
    const uint32_t dstB = (uint32_t)(brow * 128 + ((bseg ^ (brow & 7)) << 4));

    // --- ldmatrix fragment bases ---
    const int rowA = warp_m * 64 + (lid & 15);
    const uint32_t xA = (uint32_t)(rowA & 7);
    const int rowB0 = warp_n * 32 + (lid & 15);
    const int rowB1 = rowB0 + 16;
    const uint32_t xB0 = (uint32_t)(rowB0 & 7);
    const uint32_t xB1 = (uint32_t)(rowB1 & 7);
    const uint32_t hi = (uint32_t)(lid >> 4);

    float acc[4][4][4];
#pragma unroll
    for (int i = 0; i < 4; i++)
#pragma unroll
        for (int j = 0; j < 4; j++)
#pragma unroll
            for (int k = 0; k < 4; k++) acc[i][j][k] = 0.0f;

    uint32_t aF[2][4][4];
    uint32_t bF[2][4];
    float f2a = 0.0f, f2b = 0.0f;
    float4 v0, v1, v2, v3;

    // ---------- prologue (stages kbeg, kbeg+1) ----------
    {
        const size_t k0 = (size_t)kbeg * BK;
#pragma unroll
        for (int i = 0; i < 8; i++) cp16(sAu + soA + i * 4096, gA + (size_t)(32 * i) * DDIM + k0);
        CP_COMMIT();
#pragma unroll
        for (int i = 0; i < 8; i++)
            cp16(sAu + A_STAGE_BYTES + soA + i * 4096, gA + (size_t)(32 * i) * DDIM + k0 + BK);
        CP_COMMIT();
        v0 = *(const float4*)(gB0 + k0);
        v1 = *(const float4*)(gB0 + k0 + 4);
        v2 = *(const float4*)(gB1 + k0);
        v3 = *(const float4*)(gB1 + k0 + 4);
        CP_WAIT1();
        f2a += v0.x*v0.x + v0.y*v0.y + v0.z*v0.z + v0.w*v0.w
             + v1.x*v1.x + v1.y*v1.y + v1.z*v1.z + v1.w*v1.w;
        f2b += v2.x*v2.x + v2.y*v2.y + v2.z*v2.z + v2.w*v2.w
             + v3.x*v3.x + v3.y*v3.y + v3.z*v3.z + v3.w*v3.w;
        __nv_bfloat162 p0 = __floats2bfloat162_rn(v0.x, v0.y);
        __nv_bfloat162 p1 = __floats2bfloat162_rn(v0.z, v0.w);
        __nv_bfloat162 p2 = __floats2bfloat162_rn(v1.x, v1.y);
        __nv_bfloat162 p3 = __floats2bfloat162_rn(v1.z, v1.w);
        sts128u(sBcu + dstB, *(uint32_t*)&p0, *(uint32_t*)&p1, *(uint32_t*)&p2, *(uint32_t*)&p3);
        p0 = __floats2bfloat162_rn(v2.x, v2.y);
        p1 = __floats2bfloat162_rn(v2.z, v2.w);
        p2 = __floats2bfloat162_rn(v3.x, v3.y);
        p3 = __floats2bfloat162_rn(v3.z, v3.w);
        sts128u(sBcu + dstB + 32 * 128, *(uint32_t*)&p0, *(uint32_t*)&p1, *(uint32_t*)&p2, *(uint32_t*)&p3);
        v0 = *(const float4*)(gB0 + k0 + BK);
        v1 = *(const float4*)(gB0 + k0 + BK + 4);
        v2 = *(const float4*)(gB1 + k0 + BK);
        v3 = *(const float4*)(gB1 + k0 + BK + 4);
    }
    __syncthreads();

    // ---------- mainloop: convert/prefetch hoisted BEFORE the mma burst ----------
    int stage = 0;
    for (int it = 0; it < nk; it++) {
        const uint32_t abase = sAu + (uint32_t)stage * A_STAGE_BYTES;
        const uint32_t bbase = sBcu + (uint32_t)(it & 1) * B_STAGE_BYTES;

        // preload A fragments for ks=0
        {
            const uint32_t ch = hi;
#pragma unroll
            for (int mt = 0; mt < 4; mt++)
                ldsm_x4(aF[0][mt], abase + (uint32_t)((rowA + mt * 16) * 128) + ((ch ^ xA) << 4));
        }

        // commit A(it+2)
        if (it + 2 < nk) {
            const int s2 = (stage >= 1) ? stage - 1 : stage + 2;
            const size_t ko = (size_t)(kbeg + it + 2) * BK;
#pragma unroll
            for (int i = 0; i < 8; i++)
                cp16(sAu + (uint32_t)s2 * A_STAGE_BYTES + soA + i * 4096,
                     gA + (size_t)(32 * i) * DDIM + ko);
            CP_COMMIT();
        }

        // wait A(it+1); convert B(it+1) -> sBc[(it+1)&1]; load B(it+2)
        // (safe: sBc[(it+1)&1] was last read at it-1; published by it-1's barrier)
        if (it + 1 < nk) {
            if (it + 2 < nk) { CP_WAIT1(); } else { CP_WAIT0(); }
            {
                f2a += v0.x*v0.x + v0.y*v0.y + v0.z*v0.z + v0.w*v0.w
                     + v1.x*v1.x + v1.y*v1.y + v1.z*v1.z + v1.w*v1.w;
                f2b += v2.x*v2.x + v2.y*v2.y + v2.z*v2.z + v2.w*v2.w
                     + v3.x*v3.x + v3.y*v3.y + v3.z*v3.z + v3.w*v3.w;
                const uint32_t bb = sBcu + (uint32_t)((it + 1) & 1) * B_STAGE_BYTES;
                __nv_bfloat162 p0 = __floats2bfloat162_rn(v0.x, v0.y);
                __nv_bfloat162 p1 = __floats2bfloat162_rn(v0.z, v0.w);
                __nv_bfloat162 p2 = __floats2bfloat162_rn(v1.x, v1.y);
                __nv_bfloat162 p3 = __floats2bfloat162_rn(v1.z, v1.w);
                sts128u(bb + dstB, *(uint32_t*)&p0, *(uint32_t*)&p1, *(uint32_t*)&p2, *(uint32_t*)&p3);
                p0 = __floats2bfloat162_rn(v2.x, v2.y);
                p1 = __floats2bfloat162_rn(v2.z, v2.w);
                p2 = __floats2bfloat162_rn(v3.x, v3.y);
                p3 = __floats2bfloat162_rn(v3.z, v3.w);
                sts128u(bb + dstB + 32 * 128, *(uint32_t*)&p0, *(uint32_t*)&p1, *(uint32_t*)&p2, *(uint32_t*)&p3);
            }
            if (it + 2 < nk) {
                const size_t ko = (size_t)(kbeg + it + 2) * BK;
                v0 = *(const float4*)(gB0 + ko);
                v1 = *(const float4*)(gB0 + ko + 4);
                v2 = *(const float4*)(gB1 + ko);
                v3 = *(const float4*)(gB1 + ko + 4);
            }
        }

        // mma burst
#pragma unroll
        for (int ks = 0; ks < 4; ks++) {
            const int cur = ks & 1;
            {
                const uint32_t ch = (uint32_t)(ks * 2) + hi;
                ldsm_x4(bF[0], bbase + (uint32_t)(rowB0 * 128) + ((ch ^ xB0) << 4));
                ldsm_x4(bF[1], bbase + (uint32_t)(rowB1 * 128) + ((ch ^ xB1) << 4));
            }
            if (ks < 3) {
                const uint32_t ch = (uint32_t)((ks + 1) * 2) + hi;
#pragma unroll
                for (int mt = 0; mt < 4; mt++)
                    ldsm_x4(aF[cur ^ 1][mt],
                            abase + (uint32_t)((rowA + mt * 16) * 128) + ((ch ^ xA) << 4));
            }
#pragma unroll
            for (int mt = 0; mt < 4; mt++)
#pragma unroll
                for (int nt = 0; nt < 4; nt++)
                    mma16816(acc[mt][nt], aF[cur][mt], bF[nt >> 1][nt & 1], bF[nt >> 1][2 + (nt & 1)]);
        }

        if (it + 1 < nk) __syncthreads();
        stage = (stage >= 2) ? 0 : stage + 1;
    }

    // ---- f2 output ----
    f2a += __shfl_down_sync(0xffffffffu, f2a, 4, 8);
    f2a += __shfl_down_sync(0xffffffffu, f2a, 2, 8);
    f2a += __shfl_down_sync(0xffffffffu, f2a, 1, 8);
    f2b += __shfl_down_sync(0xffffffffu, f2b, 4, 8);
    f2b += __shfl_down_sync(0xffffffffu, f2b, 2, 8);
    f2b += __shfl_down_sync(0xffffffffu, f2b, 1, 8);
    if (bseg == 0) {
        if (part == 0) {
            g_f2[br * NF + n0 + brow] = f2a;
            g_f2[br * NF + n0 + brow + 32] = f2b;
        } else {
            g_f2x[(part - 1) * EXCOLS + (n0 - EXCOL0) + brow] = f2a;
            g_f2x[(part - 1) * EXCOLS + (n0 - EXCOL0) + brow + 32] = f2b;
        }
    }

    // ---- C output ----
    float* Cbase;
    size_t cst;
    if (part == 0) {
        Cbase = g_dot + (size_t)(br * BSZ + warp_m * 64) * NF + n0 + warp_n * 32;
        cst = NF;
    } else {
        Cbase = g_ex + ((size_t)(part - 1) * BSZ + warp_m * 64) * EXCOLS + (n0 - EXCOL0) + warp_n * 32;
        cst = EXCOLS;
    }
    const int rr = lid >> 2;
    const int cc = (lid & 3) * 2;
#pragma unroll
    for (int mt = 0; mt < 4; mt++)
#pragma unroll
        for (int nt = 0; nt < 4; nt++) {
            float2 w0 = make_float2(acc[mt][nt][0], acc[mt][nt][1]);
            float2 w1 = make_float2(acc[mt][nt][2], acc[mt][nt][3]);
            *(float2*)&Cbase[(size_t)(mt * 16 + rr) * cst + nt * 8 + cc] = w0;
            *(float2*)&Cbase[(size_t)(mt * 16 + rr + 8) * cst + nt * 8 + cc] = w1;
        }
}

// ======================= kernel 3: per-row loss + last-block final reduce ===========
__global__ void __launch_bounds__(256) rowloss_kernel(const int* __restrict__ targets,
                                                      float* __restrict__ out) {
    const int r = blockIdx.x;
    const int br = r >> 8;
    const int b = r & 255;
    const float* drow = g_dot + (size_t)r * NF;
    const float* f2 = g_f2 + br * NF;
    const float* ex0 = g_ex + (size_t)b * EXCOLS;
    const float* ex1 = g_ex + (size_t)(BSZ + b) * EXCOLS;
    const float x2 = g_x2[r];
    const int tid = threadIdx.x;
    const bool isSplitBr = (br == 2);

    __shared__ float sm[NF];

    float s1 = 0.0f, s2 = 0.0f;
#pragma unroll 4
    for (int i = 0; i < NF / 256; i++) {
        int n = tid + i * 256;
        float dot = drow[n];
        float ff = f2[n];
        if (isSplitBr && n >= EXCOL0) {
            int e = n - EXCOL0;
            dot += ex0[e] + ex1[e];
            ff += g_f2x[e] + g_f2x[EXCOLS + e];
        }
        s1 += expf(dot * TEMP_INV);
        float d2 = x2 + ff - 2.0f * dot;
        float d = sqrtf(fmaxf(d2, 0.0f));
        float ed = expf(d);
        s2 += ed;
        sm[n] = ed;
    }
    s1 = blockReduceSum(s1);
    __shared__ float sS1;
    if (tid == 0) sS1 = s1;
    s2 = blockReduceSum(s2);
    __shared__ float sS2;
    if (tid == 0) sS2 = s2;
    __syncthreads();
    const float inv2 = 1.0f / sS2;

    float s3 = 0.0f;
#pragma unroll 4
    for (int i = 0; i < NF / 256; i++) {
        int n = tid + i * 256;
        s3 += expf(sm[n] * inv2);
    }
    s3 = blockReduceSum(s3);

    if (tid == 0) {
        int t = targets[b];
        float dott = drow[t];
        float f2t = f2[t];
        if (isSplitBr && t >= EXCOL0) {
            int e = t - EXCOL0;
            dott += ex0[e] + ex1[e];
            f2t += g_f2x[e] + g_f2x[EXCOLS + e];
        }
        float d2t = x2 + f2t - 2.0f * dott;
        float dt = sqrtf(fmaxf(d2t, 0.0f));
        float loss1 = logf(sS1) - dott * TEMP_INV;
        float loss2 = logf(s3) - expf(dt) * inv2;
        g_rowloss[r] = loss1 + loss2;
    }

    __shared__ int s_isLast;
    __threadfence();
    if (tid == 0) {
        int c = atomicAdd(&g_count, 1);
        s_isLast = (c == NB * BSZ - 1) ? 1 : 0;
    }
    __syncthreads();
    if (s_isLast) {
        float v2 = g_rowloss[tid] + g_rowloss[tid + 256] + g_rowloss[tid + 512];
        v2 = blockReduceSum(v2);
        if (tid == 0) {
            out[0] = v2 * (0.5f / 256.0f);
            g_count = 0;
        }
    }
}

// ======================= launch =======================
extern "C" void kernel_launch(void* const* d_in, const int* in_sizes, int n_in,
                              void* d_out, int out_size) {
    const float* inputs      = (const float*)d_in[0];
    const float* inputs_up   = (const float*)d_in[1];
    const float* inputs_down = (const float*)d_in[2];
    const int*   targets     = (const int*)d_in[3];
    const float* features      = (const float*)d_in[5];
    const float* features_up   = (const float*)d_in[6];
    const float* features_down = (const float*)d_in[7];
    float* out = (float*)d_out;

    cudaFuncSetAttribute(gemm_fused_kernel,
                         cudaFuncAttributeMaxDynamicSharedMemorySize, SMEM_DYN);

    prep_x_kernel<<<NB * BSZ, 256>>>(inputs, inputs_up, inputs_down);
    gemm_fused_kernel<<<NT_FULL + 88 * 3, 256, SMEM_DYN>>>(features, features_up, features_down);
    rowloss_kernel<<<NB * BSZ, 256>>>(targets, out);
}